// round 3
// baseline (speedup 1.0000x reference)
#include <cuda_runtime.h>
#include <math.h>

// Problem shape (fixed for this benchmark)
#define T_DIM 2048
#define B_DIM 8
#define C_DIM 1024
#define H_DIM 16
#define K_DIM 7
#define R_DIM 64                     // C/H
#define M_DIM (T_DIM * B_DIM)        // 16384 rows
#define NW    144                    // 112 conv-logit cols + 32 glu cols

// Scratch (allocation-free rule: __device__ globals)
__device__ float g_P[(size_t)M_DIM * NW];      // GEMM1 output: logits + glu pre-act
__device__ float g_Y[(size_t)M_DIM * C_DIM];   // conv*gate result, input to GEMM2

// ---------------------------------------------------------------------------
// SGEMM (NT): C[m*ldc + n] = sum_k A[m*K + k] * B[n*K + k] + bias[n]
// A: M x K row-major, B: N x K row-major (i.e. C = A @ B^T). 128x128x8 tile,
// 256 threads, 8x8 per-thread microtile, float4 global loads, N-edge guarded.
// ---------------------------------------------------------------------------
__global__ __launch_bounds__(256) void sgemm_nt(
    const float* __restrict__ A, const float* __restrict__ B,
    const float* __restrict__ bias, float* __restrict__ C,
    int M, int N, int K, int ldc)
{
    const int BM = 128, BN = 128, BK = 8;
    __shared__ float As[BK][BM];
    __shared__ float Bs[BK][BN];

    const int tid = threadIdx.x;
    const int bm = blockIdx.y * BM;
    const int bn = blockIdx.x * BN;
    const int tx = tid & 15;         // 0..15 -> column group
    const int ty = tid >> 4;         // 0..15 -> row group

    float acc[8][8];
    #pragma unroll
    for (int i = 0; i < 8; ++i)
        #pragma unroll
        for (int j = 0; j < 8; ++j) acc[i][j] = 0.0f;

    const int ld_row  = tid >> 1;          // 0..127
    const int ld_col4 = (tid & 1) * 4;     // 0 or 4
    const bool a_ok = (bm + ld_row) < M;
    const bool b_ok = (bn + ld_row) < N;
    const float* Aptr = A + (size_t)(bm + ld_row) * K + ld_col4;
    const float* Bptr = B + (size_t)(bn + ld_row) * K + ld_col4;

    for (int k0 = 0; k0 < K; k0 += BK) {
        float4 av = a_ok ? *(const float4*)(Aptr + k0) : make_float4(0.f, 0.f, 0.f, 0.f);
        float4 bv = b_ok ? *(const float4*)(Bptr + k0) : make_float4(0.f, 0.f, 0.f, 0.f);
        __syncthreads();
        As[ld_col4 + 0][ld_row] = av.x;
        As[ld_col4 + 1][ld_row] = av.y;
        As[ld_col4 + 2][ld_row] = av.z;
        As[ld_col4 + 3][ld_row] = av.w;
        Bs[ld_col4 + 0][ld_row] = bv.x;
        Bs[ld_col4 + 1][ld_row] = bv.y;
        Bs[ld_col4 + 2][ld_row] = bv.z;
        Bs[ld_col4 + 3][ld_row] = bv.w;
        __syncthreads();

        #pragma unroll
        for (int kk = 0; kk < BK; ++kk) {
            float ar[8], br[8];
            *(float4*)&ar[0] = *(const float4*)&As[kk][ty * 8 + 0];
            *(float4*)&ar[4] = *(const float4*)&As[kk][ty * 8 + 4];
            *(float4*)&br[0] = *(const float4*)&Bs[kk][tx * 8 + 0];
            *(float4*)&br[4] = *(const float4*)&Bs[kk][tx * 8 + 4];
            #pragma unroll
            for (int i = 0; i < 8; ++i)
                #pragma unroll
                for (int j = 0; j < 8; ++j)
                    acc[i][j] = fmaf(ar[i], br[j], acc[i][j]);
        }
    }

    #pragma unroll
    for (int i = 0; i < 8; ++i) {
        const int m = bm + ty * 8 + i;
        if (m >= M) continue;
        #pragma unroll
        for (int j = 0; j < 8; ++j) {
            const int n = bn + tx * 8 + j;
            if (n < N) {
                float bval = bias ? bias[n] : 0.0f;
                C[(size_t)m * ldc + n] = acc[i][j] + bval;
            }
        }
    }
}

// ---------------------------------------------------------------------------
// Middle stage: one warp per (t, b, h).
//   softmax over K=7 logits, GLU gate = a * sigmoid(b),
//   y[t,b,h,r] = gate * sum_k w_k * x[t + k - pad, b, h, r]
// Lanes cover r = lane, lane+32 (R=64). Coalesced x/Y access along r.
// ---------------------------------------------------------------------------
__global__ __launch_bounds__(256) void conv_gate_kernel(
    const float* __restrict__ x, const float* __restrict__ glu_b,
    const int* __restrict__ pad_p)
{
    const int warp = (blockIdx.x * blockDim.x + threadIdx.x) >> 5;
    const int lane = threadIdx.x & 31;
    if (warp >= M_DIM * H_DIM) return;

    const int h  = warp % H_DIM;
    const int m  = warp / H_DIM;     // m = t*B + b
    const int b  = m % B_DIM;
    const int t  = m / B_DIM;
    const int pad = pad_p ? *pad_p : 6;

    const float* Prow = g_P + (size_t)m * NW;

    // softmax over K logits (max-sub, matches jax.nn.softmax numerics)
    float lg[K_DIM];
    #pragma unroll
    for (int k = 0; k < K_DIM; ++k) lg[k] = Prow[h * K_DIM + k];
    float mx = lg[0];
    #pragma unroll
    for (int k = 1; k < K_DIM; ++k) mx = fmaxf(mx, lg[k]);
    float s = 0.0f;
    #pragma unroll
    for (int k = 0; k < K_DIM; ++k) { lg[k] = expf(lg[k] - mx); s += lg[k]; }
    const float inv = 1.0f / s;
    #pragma unroll
    for (int k = 0; k < K_DIM; ++k) lg[k] *= inv;

    // GLU gate
    const float ga = Prow[112 + 2 * h]     + glu_b[2 * h];
    const float gb = Prow[112 + 2 * h + 1] + glu_b[2 * h + 1];
    const float gate = ga / (1.0f + expf(-gb));

    const int base_c = h * R_DIM;
    #pragma unroll
    for (int rr = 0; rr < 2; ++rr) {
        const int r = lane + rr * 32;
        float accv = 0.0f;
        #pragma unroll
        for (int k = 0; k < K_DIM; ++k) {
            const int st = t + k - pad;
            if (st >= 0 && st < T_DIM) {
                accv = fmaf(lg[k],
                            x[((size_t)st * B_DIM + b) * C_DIM + base_c + r],
                            accv);
            }
        }
        g_Y[(size_t)m * C_DIM + base_c + r] = accv * gate;
    }
}

// ---------------------------------------------------------------------------
// Launch: GEMM1 (logits, glu) -> conv/gate -> GEMM2 (output projection)
// Inputs (metadata order): x, w_weight, glu_w, glu_b, out_w, out_b, padding_l
// ---------------------------------------------------------------------------
extern "C" void kernel_launch(void* const* d_in, const int* in_sizes, int n_in,
                              void* d_out, int out_size)
{
    const float* x        = (const float*)d_in[0];
    const float* w_weight = (const float*)d_in[1];
    const float* glu_w    = (const float*)d_in[2];
    const float* glu_b    = (const float*)d_in[3];
    const float* out_w    = (const float*)d_in[4];
    const float* out_b    = (const float*)d_in[5];
    const int*   pad_p    = (n_in > 6) ? (const int*)d_in[6] : nullptr;

    float* P = nullptr;
    float* Y = nullptr;
    cudaGetSymbolAddress((void**)&P, g_P);
    cudaGetSymbolAddress((void**)&Y, g_Y);

    // GEMM1a: conv-weight logits  P[:, 0:112] = x @ w_weight^T
    {
        dim3 grid((112 + 127) / 128, M_DIM / 128);
        sgemm_nt<<<grid, 256>>>(x, w_weight, nullptr, P, M_DIM, 112, C_DIM, NW);
    }
    // GEMM1b: GLU pre-activation  P[:, 112:144] = x @ glu_w^T
    {
        dim3 grid((32 + 127) / 128, M_DIM / 128);
        sgemm_nt<<<grid, 256>>>(x, glu_w, nullptr, P + 112, M_DIM, 32, C_DIM, NW);
    }
    // Middle: softmax + gate + depthwise dynamic conv -> Y
    {
        const int total_warps = M_DIM * H_DIM;      // 262144
        const int blocks = (total_warps * 32 + 255) / 256;
        conv_gate_kernel<<<blocks, 256>>>(x, glu_b, pad_p);
    }
    // GEMM2: out = Y @ out_w^T + out_b
    {
        dim3 grid(C_DIM / 128, M_DIM / 128);
        sgemm_nt<<<grid, 256>>>(Y, out_w, out_b, (float*)d_out,
                                M_DIM, C_DIM, C_DIM, C_DIM);
    }
}

// round 7
// speedup vs baseline: 3.0251x; 3.0251x over previous
#include <cuda_runtime.h>
#include <math.h>
#include <stdint.h>

// Problem shape (fixed)
#define T_DIM 2048
#define B_DIM 8
#define C_DIM 1024
#define H_DIM 16
#define K_DIM 7
#define R_DIM 64
#define M_DIM (T_DIM * B_DIM)        // 16384
#define NW    144
#define GK    1024                   // K dim of every GEMM here

__device__ float g_P[(size_t)M_DIM * NW];      // GEMM1 out: logits + glu pre-act
__device__ float g_Y[(size_t)M_DIM * C_DIM];   // conv*gate result

__device__ __forceinline__ uint32_t f2tf32(float f) {
    uint32_t u;
    asm("cvt.rna.tf32.f32 %0, %1;" : "=r"(u) : "f"(f));
    return u;
}

// ===========================================================================
// tf32 mma.sync GEMM (NT): C[m*ldc+n] = sum_k A[m,k]*B[n,k] (+bias[n])
// M multiple of 128 (always 16384 here), K = 1024, N arbitrary (guarded),
// N assumed multiple of 16 for the paired stores (112 / 32 / 1024 all are).
// Block: 256 threads = 8 warps in 2(m) x 4(n) grid; warp tile 64x32;
// per warp 4x4 m16n8k8 fragments. BK=32. Smem row stride 36 floats makes
// every fragment gather perfectly bank-distributed ((4r+c) mod 32 bijective).
// ===========================================================================
__global__ __launch_bounds__(256, 2) void gemm_mma_tf32(
    const float* __restrict__ A, const float* __restrict__ B,
    const float* __restrict__ bias, float* __restrict__ C,
    int N, int ldc)
{
    __shared__ uint32_t As[128][36];
    __shared__ uint32_t Bs[128][36];

    const int tid  = threadIdx.x;
    const int lane = tid & 31;
    const int wid  = tid >> 5;
    const int warp_m = (wid >> 2) * 64;   // 0 or 64
    const int warp_n = (wid & 3) * 32;    // 0,32,64,96
    const int bm = blockIdx.y * 128;
    const int bn = blockIdx.x * 128;

    float acc[4][4][4];
    #pragma unroll
    for (int i = 0; i < 4; ++i)
        #pragma unroll
        for (int j = 0; j < 4; ++j)
            #pragma unroll
            for (int q = 0; q < 4; ++q) acc[i][j][q] = 0.0f;

    const int r = lane >> 2;       // 0..7
    const int c = lane & 3;        // 0..3

    for (int k0 = 0; k0 < GK; k0 += 32) {
        // ---- stage A/B tiles (128 x 32 f32 each) with tf32 rounding ----
        #pragma unroll
        for (int i = 0; i < 4; ++i) {
            const int idx = tid + i * 256;        // 0..1023
            const int row = idx >> 3;             // 0..127
            const int c4  = (idx & 7) * 4;        // 0..28
            const float4 av = *(const float4*)(A + (size_t)(bm + row) * GK + k0 + c4);
            float4 bv = make_float4(0.f, 0.f, 0.f, 0.f);
            if (bn + row < N)
                bv = *(const float4*)(B + (size_t)(bn + row) * GK + k0 + c4);
            As[row][c4 + 0] = f2tf32(av.x);
            As[row][c4 + 1] = f2tf32(av.y);
            As[row][c4 + 2] = f2tf32(av.z);
            As[row][c4 + 3] = f2tf32(av.w);
            Bs[row][c4 + 0] = f2tf32(bv.x);
            Bs[row][c4 + 1] = f2tf32(bv.y);
            Bs[row][c4 + 2] = f2tf32(bv.z);
            Bs[row][c4 + 3] = f2tf32(bv.w);
        }
        __syncthreads();

        // ---- compute: 4 k8 steps, 16 mma each ----
        #pragma unroll
        for (int ks = 0; ks < 4; ++ks) {
            const int kk = ks * 8;
            uint32_t a[4][4], b[4][2];
            #pragma unroll
            for (int i = 0; i < 4; ++i) {
                const int mr = warp_m + i * 16 + r;
                a[i][0] = As[mr][kk + c];
                a[i][1] = As[mr + 8][kk + c];
                a[i][2] = As[mr][kk + c + 4];
                a[i][3] = As[mr + 8][kk + c + 4];
            }
            #pragma unroll
            for (int j = 0; j < 4; ++j) {
                const int nr = warp_n + j * 8 + r;   // col (n) = groupID
                b[j][0] = Bs[nr][kk + c];            // row (k) = threadID_in_group
                b[j][1] = Bs[nr][kk + c + 4];
            }
            #pragma unroll
            for (int i = 0; i < 4; ++i)
                #pragma unroll
                for (int j = 0; j < 4; ++j)
                    asm volatile(
                        "mma.sync.aligned.m16n8k8.row.col.f32.tf32.tf32.f32 "
                        "{%0,%1,%2,%3}, {%4,%5,%6,%7}, {%8,%9}, {%0,%1,%2,%3};"
                        : "+f"(acc[i][j][0]), "+f"(acc[i][j][1]),
                          "+f"(acc[i][j][2]), "+f"(acc[i][j][3])
                        : "r"(a[i][0]), "r"(a[i][1]), "r"(a[i][2]), "r"(a[i][3]),
                          "r"(b[j][0]), "r"(b[j][1]));
        }
        __syncthreads();
    }

    // ---- epilogue: paired f32x2 stores, guarded on N ----
    const int c2 = c * 2;
    #pragma unroll
    for (int i = 0; i < 4; ++i) {
        const int m0 = bm + warp_m + i * 16 + r;
        #pragma unroll
        for (int j = 0; j < 4; ++j) {
            const int n = bn + warp_n + j * 8 + c2;
            if (n < N) {
                const float b0v = bias ? bias[n]     : 0.0f;
                const float b1v = bias ? bias[n + 1] : 0.0f;
                float2 v0 = make_float2(acc[i][j][0] + b0v, acc[i][j][1] + b1v);
                float2 v1 = make_float2(acc[i][j][2] + b0v, acc[i][j][3] + b1v);
                *(float2*)(C + (size_t)m0 * ldc + n)       = v0;
                *(float2*)(C + (size_t)(m0 + 8) * ldc + n) = v1;
            }
        }
    }
}

// ===========================================================================
// Middle stage: one warp per (t, b, h): softmax(K=7) + GLU gate + depthwise
// dynamic conv. Lanes cover r = lane, lane+32.
// ===========================================================================
__global__ __launch_bounds__(256) void conv_gate_kernel(
    const float* __restrict__ x, const float* __restrict__ glu_b,
    const int* __restrict__ pad_p)
{
    const int warp = (blockIdx.x * blockDim.x + threadIdx.x) >> 5;
    const int lane = threadIdx.x & 31;
    if (warp >= M_DIM * H_DIM) return;

    const int h  = warp % H_DIM;
    const int m  = warp / H_DIM;
    const int b  = m % B_DIM;
    const int t  = m / B_DIM;
    const int pad = pad_p ? *pad_p : 6;

    const float* Prow = g_P + (size_t)m * NW;

    float lg[K_DIM];
    #pragma unroll
    for (int k = 0; k < K_DIM; ++k) lg[k] = Prow[h * K_DIM + k];
    float mx = lg[0];
    #pragma unroll
    for (int k = 1; k < K_DIM; ++k) mx = fmaxf(mx, lg[k]);
    float s = 0.0f;
    #pragma unroll
    for (int k = 0; k < K_DIM; ++k) { lg[k] = expf(lg[k] - mx); s += lg[k]; }
    const float inv = 1.0f / s;
    #pragma unroll
    for (int k = 0; k < K_DIM; ++k) lg[k] *= inv;

    const float ga = Prow[112 + 2 * h]     + glu_b[2 * h];
    const float gb = Prow[112 + 2 * h + 1] + glu_b[2 * h + 1];
    const float gate = ga / (1.0f + expf(-gb));

    const int base_c = h * R_DIM;
    #pragma unroll
    for (int rr = 0; rr < 2; ++rr) {
        const int r = lane + rr * 32;
        float accv = 0.0f;
        #pragma unroll
        for (int k = 0; k < K_DIM; ++k) {
            const int st = t + k - pad;
            if (st >= 0 && st < T_DIM) {
                accv = fmaf(lg[k],
                            x[((size_t)st * B_DIM + b) * C_DIM + base_c + r],
                            accv);
            }
        }
        g_Y[(size_t)m * C_DIM + base_c + r] = accv * gate;
    }
}

// ===========================================================================
// Launch: GEMM1a/1b (tf32 mma) -> conv/gate -> GEMM2 (tf32 mma)
// Inputs: x, w_weight, glu_w, glu_b, out_w, out_b, padding_l
// ===========================================================================
extern "C" void kernel_launch(void* const* d_in, const int* in_sizes, int n_in,
                              void* d_out, int out_size)
{
    const float* x        = (const float*)d_in[0];
    const float* w_weight = (const float*)d_in[1];
    const float* glu_w    = (const float*)d_in[2];
    const float* glu_b    = (const float*)d_in[3];
    const float* out_w    = (const float*)d_in[4];
    const float* out_b    = (const float*)d_in[5];
    const int*   pad_p    = (n_in > 6) ? (const int*)d_in[6] : nullptr;

    float* P = nullptr;
    float* Y = nullptr;
    cudaGetSymbolAddress((void**)&P, g_P);
    cudaGetSymbolAddress((void**)&Y, g_Y);

    // GEMM1a: conv-weight logits  P[:, 0:112] = x @ w_weight^T
    gemm_mma_tf32<<<dim3(1, M_DIM / 128), 256>>>(x, w_weight, nullptr, P, 112, NW);
    // GEMM1b: GLU pre-activation  P[:, 112:144] = x @ glu_w^T
    gemm_mma_tf32<<<dim3(1, M_DIM / 128), 256>>>(x, glu_w, nullptr, P + 112, 32, NW);
    // Middle stage
    {
        const int total_warps = M_DIM * H_DIM;
        const int blocks = (total_warps * 32 + 255) / 256;
        conv_gate_kernel<<<blocks, 256>>>(x, glu_b, pad_p);
    }
    // GEMM2: out = Y @ out_w^T + out_b
    gemm_mma_tf32<<<dim3(C_DIM / 128, M_DIM / 128), 256>>>(Y, out_w, out_b,
                                                           (float*)d_out,
                                                           C_DIM, C_DIM);
}